// round 10
// baseline (speedup 1.0000x reference)
#include <cuda_runtime.h>
#include <math.h>
#include <stdint.h>

#define N_NODES 50000
#define FDIM    200
#define E1C     400000
#define E2C     100000
#define E_TOT   500000
#define ALPHA   0.2f

// tensor-GEMM tiling
#define BM 128
#define BK 40
#define NKB 5
#define AS_STRIDE 44          // conflict-free A frag loads
#define BP_STRIDE 202         // float4 units; (2*lc+lr) mod 8 distinct -> conflict-free LDS.128
#define A_BUF (BM * AS_STRIDE)            // floats
#define B_BUF4 (20 * BP_STRIDE)           // float4 per buffer (5 kk * 4 jj rows)
#define SMEM_FLOATS (2 * A_BUF + 2 * B_BUF4 * 4)
#define SMEM_BYTES  (SMEM_FLOATS * 4)

// ---- device scratch ----
__device__ float g_X1[(size_t)N_NODES * FDIM];
__device__ float g_X2[(size_t)N_NODES * FDIM];
// g_accum: [0,10M) = ACC; [10M,20M) = G; [20M,20M+N) = rowsum
__device__ float g_accum[2 * (size_t)N_NODES * FDIM + N_NODES];
__device__ float g_p[4 * N_NODES];
__device__ float g_v[600];
__device__ float g_w[600];
__device__ float4 g_bp[75 * 4 * FDIM];   // packed B: [jb][jj][o] = {hi(j),hi(j+4),lo(j),lo(j+4)}
__device__ float g_ee[E_TOT];
__device__ int  g_deg[N_NODES];
__device__ int  g_off[N_NODES + 1];
__device__ int  g_cur[N_NODES];
__device__ int2 g_rec[E_TOT];    // (dst, eid)
__device__ int4 g_rec3[E_TOT];   // (dst, eid, ee_bits, 0)

#define ACC_OFF  ((size_t)0)
#define G_OFF    ((size_t)N_NODES * FDIM)
#define RS_OFF   (2 * (size_t)N_NODES * FDIM)

__device__ __forceinline__ float dot4(float4 a, float4 b) {
    return a.x * b.x + a.y * b.y + a.z * b.z + a.w * b.w;
}

__device__ __forceinline__ float to_tf32(float x) {
    uint32_t u;
    asm("cvt.rna.tf32.f32 %0, %1;" : "=r"(u) : "f"(x));
    return __uint_as_float(u);
}

__device__ __forceinline__ float tanh_fast(float x) {
    float y;
    asm("tanh.approx.f32 %0, %1;" : "=f"(y) : "f"(x));
    return y;
}

__device__ __forceinline__ void mma_tf32(float* c, const uint32_t* a, uint32_t b0, uint32_t b1) {
    asm volatile("mma.sync.aligned.m16n8k8.row.col.f32.tf32.tf32.f32 "
                 "{%0,%1,%2,%3}, {%4,%5,%6,%7}, {%8,%9}, {%0,%1,%2,%3};"
                 : "+f"(c[0]), "+f"(c[1]), "+f"(c[2]), "+f"(c[3])
                 : "r"(a[0]), "r"(a[1]), "r"(a[2]), "r"(a[3]), "r"(b0), "r"(b1));
}

__device__ __forceinline__ void cp_async16(void* smem_dst, const void* gmem_src, bool pred) {
    uint32_t s = (uint32_t)__cvta_generic_to_shared(smem_dst);
    int sz = pred ? 16 : 0;
    asm volatile("cp.async.cg.shared.global [%0], [%1], 16, %2;"
                 :: "r"(s), "l"(gmem_src), "r"(sz));
}
__device__ __forceinline__ void cp_commit() {
    asm volatile("cp.async.commit_group;");
}
template<int N>
__device__ __forceinline__ void cp_wait() {
    asm volatile("cp.async.wait_group %0;" :: "n"(N));
}

// ---------------- CSR build ----------------
__global__ __launch_bounds__(256) void zero_deg_kernel() {
    int i = blockIdx.x * blockDim.x + threadIdx.x;
    if (i < N_NODES) g_deg[i] = 0;
}

__global__ __launch_bounds__(256) void deg_kernel(const int* __restrict__ edge,
                                                  const int* __restrict__ edge2) {
    int e = blockIdx.x * blockDim.x + threadIdx.x;
    if (e >= E_TOT) return;
    int src = (e < E1C) ? edge[e] : edge2[e - E1C];
    atomicAdd(&g_deg[src], 1);
}

__global__ __launch_bounds__(1024) void scan_kernel() {
    __shared__ int warp_sums[32];
    __shared__ int s_total;
    __shared__ int s_run;
    int t = threadIdx.x;
    int lane = t & 31, wid = t >> 5;
    if (t == 0) s_run = 0;
    __syncthreads();
    for (int base = 0; base < N_NODES; base += 1024) {
        int idx = base + t;
        int v = (idx < N_NODES) ? g_deg[idx] : 0;
        int incl = v;
        #pragma unroll
        for (int d = 1; d < 32; d <<= 1) {
            int n = __shfl_up_sync(0xffffffffu, incl, d);
            if (lane >= d) incl += n;
        }
        if (lane == 31) warp_sums[wid] = incl;
        __syncthreads();
        if (wid == 0) {
            int ws = warp_sums[lane];
            int wincl = ws;
            #pragma unroll
            for (int d = 1; d < 32; d <<= 1) {
                int n = __shfl_up_sync(0xffffffffu, wincl, d);
                if (lane >= d) wincl += n;
            }
            warp_sums[lane] = wincl - ws;
            if (lane == 31) s_total = wincl;
        }
        __syncthreads();
        int excl = s_run + warp_sums[wid] + incl - v;
        if (idx < N_NODES) { g_off[idx] = excl; g_cur[idx] = excl; }
        __syncthreads();
        if (t == 0) s_run += s_total;
        __syncthreads();
    }
    if (t == 0) g_off[N_NODES] = s_run;
}

__global__ __launch_bounds__(256) void fill_kernel(const int* __restrict__ edge,
                                                   const int* __restrict__ edge2) {
    int e = blockIdx.x * blockDim.x + threadIdx.x;
    if (e >= E_TOT) return;
    int src, dst;
    if (e < E1C) { src = edge[e]; dst = edge[E1C + e]; }
    else         { src = edge2[e - E1C]; dst = edge2[E2C + (e - E1C)]; }
    int pos = atomicAdd(&g_cur[src], 1);
    g_rec[pos] = make_int2(dst, e);
}

// ---------------- pack (dst, eid, ee) ----------------
__global__ __launch_bounds__(256) void pack_kernel() {
    int i = blockIdx.x * blockDim.x + threadIdx.x;
    if (i >= E_TOT) return;
    int2 r = g_rec[i];
    float e = g_ee[r.y];
    g_rec3[i] = make_int4(r.x, r.y, __float_as_int(e), 0);
}

// ---------------- weights prep: packed tf32 hi/lo pairs ----------------
// g_bp[(jb*4+jj)*200+o] = {hi(a^T[jb*8+jj][o]), hi(a^T[jb*8+jj+4][o]),
//                          lo(...same j...),    lo(...j+4...)}
__global__ __launch_bounds__(256) void transpose_kernel(const float* __restrict__ a) {
    int i = blockIdx.x * blockDim.x + threadIdx.x;
    if (i >= 75 * 4 * FDIM) return;
    int jb = i / (4 * FDIM);
    int r  = i % (4 * FDIM);
    int jj = r / FDIM;
    int o  = r % FDIM;
    int j0 = jb * 8 + jj;
    int j1 = j0 + 4;
    float v0 = a[o * 600 + j0];
    float v1 = a[o * 600 + j1];
    float h0 = to_tf32(v0);
    float h1 = to_tf32(v1);
    g_bp[i] = make_float4(h0, h1, to_tf32(v0 - h0), to_tf32(v1 - h1));
}

__global__ __launch_bounds__(640) void vw_kernel(const float* __restrict__ a,
                                                 const float* __restrict__ a2,
                                                 const float* __restrict__ mw) {
    int j = threadIdx.x;
    if (j >= 600) return;
    float v = 0.f, w = 0.f;
    for (int o = 0; o < FDIM; o++) {
        float aj = a[o * 600 + j];
        v += aj * a2[o];
        w += aj * mw[o];
    }
    g_v[j] = v;
    g_w[j] = w;
}

__global__ __launch_bounds__(256) void pvec_kernel(const float* __restrict__ x) {
    __shared__ float4 sv[100];
    __shared__ float4 sw[100];
    int t = threadIdx.x;
    if (t < 100)       sv[t]       = ((const float4*)g_v)[t];
    else if (t < 200)  sw[t - 100] = ((const float4*)g_w)[t - 100];
    __syncthreads();

    int warp = t >> 5, lane = t & 31;
    int node = blockIdx.x * 8 + warp;
    if (node >= N_NODES) return;

    const float4* xr = (const float4*)x + (size_t)node * 50;
    float4 x0 = xr[lane];
    float4 x1 = (lane < 18) ? xr[32 + lane] : make_float4(0, 0, 0, 0);

    float p1  = dot4(x0, sv[lane])      + ((lane < 18) ? dot4(x1, sv[32 + lane]) : 0.f);
    float p2  = dot4(x0, sv[50 + lane]) + ((lane < 18) ? dot4(x1, sv[82 + lane]) : 0.f);
    float pm1 = dot4(x0, sw[lane])      + ((lane < 18) ? dot4(x1, sw[32 + lane]) : 0.f);
    float pm2 = dot4(x0, sw[50 + lane]) + ((lane < 18) ? dot4(x1, sw[82 + lane]) : 0.f);

    #pragma unroll
    for (int off = 16; off; off >>= 1) {
        p1  += __shfl_xor_sync(0xffffffffu, p1, off);
        p2  += __shfl_xor_sync(0xffffffffu, p2, off);
        pm1 += __shfl_xor_sync(0xffffffffu, pm1, off);
        pm2 += __shfl_xor_sync(0xffffffffu, pm2, off);
    }
    if (lane == 0) {
        g_p[node]               = p1;
        g_p[N_NODES + node]     = p2;
        g_p[2 * N_NODES + node] = pm1;
        g_p[3 * N_NODES + node] = pm2;
    }
}

// ---------------- tensor-core GEMM (3xTF32, packed B, 4mt x 7nt warps) ----------------
__device__ __forceinline__ void stage_tile(float* As, float4* Bs,
                                           const float* In, int M, int row0,
                                           int at_jb, int k0jb, int t) {
    // A: 128 rows x 40 cols = 1280 float4
    #pragma unroll
    for (int i = 0; i < 5; i++) {
        int idx = t + i * 256;
        int r = idx / 10, c4 = idx % 10;
        cp_async16(As + r * AS_STRIDE + c4 * 4,
                   In + (size_t)(row0 + r) * FDIM + k0jb * 8 + c4 * 4,
                   row0 + r < M);
    }
    // B packed: 5 jb * 4 jj * 200 o float4 = 4000
    const float4* src = g_bp + (size_t)(at_jb + k0jb) * 4 * FDIM;
    #pragma unroll
    for (int i = 0; i < 16; i++) {
        int idx = t + i * 256;
        if (idx < 4000) {
            int row = idx / FDIM, o = idx % FDIM;
            cp_async16(Bs + row * BP_STRIDE + o, src + idx, true);
        }
    }
}

// dest 0 -> g_X1, 1 -> g_X2, 2 -> final epilogue into fout
__global__ void __launch_bounds__(256, 1)
tgemm_kernel(const float* __restrict__ in, int M, int at_jb, int dest,
             float* __restrict__ fout) {
    extern __shared__ float sm_[];
    float* As[2]   = { sm_, sm_ + A_BUF };
    float4* Bs4[2] = { (float4*)(sm_ + 2 * A_BUF),
                       (float4*)(sm_ + 2 * A_BUF) + B_BUF4 };

    const float* In = (dest == 2) ? (g_accum + G_OFF) : in;
    int row0 = blockIdx.x * BM;
    int t = threadIdx.x;
    int warp = t >> 5, lane = t & 31;
    int mg = warp >> 2;            // 0..1 -> m offset mg*64 (4 tiles of 16)
    int ng = warp & 3;             // 0..3 -> n offset ng*48 (7 tiles of 8, overlapping)
    int n0 = ng * 48;
    int m0w = mg * 64;
    int lr = lane >> 2;
    int lc = lane & 3;

    float acc[4][7][4];
    #pragma unroll
    for (int a_ = 0; a_ < 4; a_++)
        #pragma unroll
        for (int b_ = 0; b_ < 7; b_++)
            #pragma unroll
            for (int c_ = 0; c_ < 4; c_++) acc[a_][b_][c_] = 0.f;

    stage_tile(As[0], Bs4[0], In, M, row0, at_jb, 0, t);
    cp_commit();

    for (int kb = 0; kb < NKB; kb++) {
        int cur = kb & 1;
        if (kb + 1 < NKB) {
            stage_tile(As[cur ^ 1], Bs4[cur ^ 1], In, M, row0, at_jb, (kb + 1) * 5, t);
            cp_commit();
            cp_wait<1>();
        } else {
            cp_wait<0>();
        }
        __syncthreads();

        const float* Ac = As[cur];
        const float4* Bc = Bs4[cur];

        #pragma unroll
        for (int kk = 0; kk < 5; kk++) {
            int ks = kk * 8;
            uint32_t ah[4][4], al[4][4];
            #pragma unroll
            for (int mt = 0; mt < 4; mt++) {
                int mrow = m0w + mt * 16 + lr;
                float r0 = Ac[mrow * AS_STRIDE + ks + lc];
                float r1 = Ac[(mrow + 8) * AS_STRIDE + ks + lc];
                float r2 = Ac[mrow * AS_STRIDE + ks + lc + 4];
                float r3 = Ac[(mrow + 8) * AS_STRIDE + ks + lc + 4];
                float h0 = to_tf32(r0), h1 = to_tf32(r1), h2 = to_tf32(r2), h3 = to_tf32(r3);
                ah[mt][0] = __float_as_uint(h0);
                ah[mt][1] = __float_as_uint(h1);
                ah[mt][2] = __float_as_uint(h2);
                ah[mt][3] = __float_as_uint(h3);
                al[mt][0] = __float_as_uint(to_tf32(r0 - h0));
                al[mt][1] = __float_as_uint(to_tf32(r1 - h1));
                al[mt][2] = __float_as_uint(to_tf32(r2 - h2));
                al[mt][3] = __float_as_uint(to_tf32(r3 - h3));
            }
            #pragma unroll
            for (int nt = 0; nt < 7; nt++) {
                int nc = n0 + nt * 8 + lr;
                float4 bf = Bc[(kk * 4 + lc) * BP_STRIDE + nc];
                uint32_t bh0 = __float_as_uint(bf.x);
                uint32_t bh1 = __float_as_uint(bf.y);
                uint32_t bl0 = __float_as_uint(bf.z);
                uint32_t bl1 = __float_as_uint(bf.w);
                #pragma unroll
                for (int mt = 0; mt < 4; mt++) {
                    mma_tf32(acc[mt][nt], ah[mt], bh0, bh1);
                    mma_tf32(acc[mt][nt], ah[mt], bl0, bl1);
                    mma_tf32(acc[mt][nt], al[mt], bh0, bh1);
                }
            }
        }
        __syncthreads();
    }

    if (dest != 2) {
        float* Out = (dest == 0) ? g_X1 : g_X2;
        #pragma unroll
        for (int mt = 0; mt < 4; mt++) {
            int r0 = row0 + m0w + mt * 16 + lr;
            #pragma unroll
            for (int nt = 0; nt < 7; nt++) {
                int col = n0 + nt * 8 + 2 * lc;
                if (col >= FDIM) continue;
                if (r0 < M)
                    *(float2*)(Out + (size_t)r0 * FDIM + col) =
                        make_float2(acc[mt][nt][0], acc[mt][nt][1]);
                if (r0 + 8 < M)
                    *(float2*)(Out + (size_t)(r0 + 8) * FDIM + col) =
                        make_float2(acc[mt][nt][2], acc[mt][nt][3]);
            }
        }
    } else {
        const float* rows = g_accum + RS_OFF;
        #pragma unroll
        for (int mt = 0; mt < 4; mt++) {
            #pragma unroll
            for (int h = 0; h < 2; h++) {
                int r = row0 + m0w + mt * 16 + lr + 8 * h;
                if (r >= M) continue;
                float rs = rows[r];
                if (rs == 0.f) {
                    #pragma unroll
                    for (int nt = 0; nt < 7; nt++) {
                        int col = n0 + nt * 8 + 2 * lc;
                        if (col >= FDIM) continue;
                        *(float2*)(fout + (size_t)r * FDIM + col) = make_float2(0.f, 0.f);
                    }
                } else {
                    float inv = 1.f / rs;
                    #pragma unroll
                    for (int nt = 0; nt < 7; nt++) {
                        int col = n0 + nt * 8 + 2 * lc;
                        if (col >= FDIM) continue;
                        size_t idx = (size_t)r * FDIM + col;
                        float2 x1 = *(const float2*)(g_X1 + idx);
                        float2 av = *(const float2*)(g_accum + ACC_OFF + idx);
                        float g0 = acc[mt][nt][2 * h + 0];
                        float g1 = acc[mt][nt][2 * h + 1];
                        float v0 = x1.x + (av.x + g0) * inv;
                        float v1 = x1.y + (av.y + g1) * inv;
                        v0 = (v0 > 0.f) ? v0 : (expf(v0) - 1.f);
                        v1 = (v1 > 0.f) ? v1 : (expf(v1) - 1.f);
                        *(float2*)(fout + idx) = make_float2(v0, v1);
                    }
                }
            }
        }
    }
}

// ---------------- phase 1: streaming edge scores ----------------
__global__ __launch_bounds__(256) void score_kernel(const int* __restrict__ edge,
                                                    const float* __restrict__ emb1,
                                                    const int* __restrict__ edge2,
                                                    const float* __restrict__ emb2,
                                                    const float* __restrict__ mlp_b) {
    __shared__ float4 sv[50];
    __shared__ float4 sw[50];
    int t = threadIdx.x;
    if (t < 50)       sv[t]      = *(const float4*)&g_v[400 + t * 4];
    else if (t < 100) sw[t - 50] = *(const float4*)&g_w[400 + (t - 50) * 4];
    __syncthreads();

    int warp = t >> 5, lane = t & 31;
    int eid = blockIdx.x * 8 + warp;
    if (eid >= E_TOT) return;

    int src, dst;
    const float4* emb;
    if (eid < E1C) {
        src = edge[eid];
        dst = edge[E1C + eid];
        emb = (const float4*)emb1 + (size_t)eid * 50;
    } else {
        int e2 = eid - E1C;
        src = edge2[e2];
        dst = edge2[E2C + e2];
        emb = (const float4*)emb2 + (size_t)e2 * 50;
    }

    float4 m0 = emb[lane];
    float4 m1 = (lane < 18) ? emb[32 + lane] : make_float4(0, 0, 0, 0);

    float q3 = dot4(m0, sv[lane]) + ((lane < 18) ? dot4(m1, sv[32 + lane]) : 0.f);
    float qm = dot4(m0, sw[lane]) + ((lane < 18) ? dot4(m1, sw[32 + lane]) : 0.f);
    #pragma unroll
    for (int off = 16; off; off >>= 1) {
        q3 += __shfl_xor_sync(0xffffffffu, q3, off);
        qm += __shfl_xor_sync(0xffffffffu, qm, off);
    }

    if (lane == 0) {
        float sa = g_p[src] + g_p[N_NODES + dst] + q3;
        float sm = g_p[2 * N_NODES + src] + g_p[3 * N_NODES + dst] + qm + mlp_b[0];
        float lrv = (sa > 0.f) ? sa : ALPHA * sa;
        float pw = -lrv * tanh_fast(sm) * (1.0f / (float)E_TOT);
        g_ee[eid] = __expf(pw);
    }
}

// ---------------- phase 2: role-split gather, packed recs, 4-edge unroll ----------------
__global__ __launch_bounds__(256) void gather_kernel(const float* __restrict__ emb1,
                                                     const float* __restrict__ emb2) {
    int t = threadIdx.x;
    int warp = t >> 5, lane = t & 31;
    int node = blockIdx.x * 4 + (warp >> 1);
    int role = warp & 1;
    if (node >= N_NODES) return;

    int beg = g_off[node];
    int end = g_off[node + 1];

    float4 a0 = make_float4(0, 0, 0, 0), a1 = a0;
    float rs = 0.f;

    for (int base = beg; base < end; base += 32) {
        int cnt = min(32, end - base);
        int4 rr = (lane < cnt) ? g_rec3[base + lane] : make_int4(0, 0, 0, 0);

        int j = 0;
        for (; j + 4 <= cnt; j += 4) {
            const float4* p[4];
            float e[4];
            #pragma unroll
            for (int k = 0; k < 4; k++) {
                int dstk = __shfl_sync(0xffffffffu, rr.x, j + k);
                int eidk = __shfl_sync(0xffffffffu, rr.y, j + k);
                e[k] = __int_as_float(__shfl_sync(0xffffffffu, rr.z, j + k));
                if (role == 0) {
                    p[k] = (eidk < E1C) ? (const float4*)emb1 + (size_t)eidk * 50
                                        : (const float4*)emb2 + (size_t)(eidk - E1C) * 50;
                } else {
                    p[k] = (const float4*)g_X2 + (size_t)dstk * 50;
                }
            }
            float4 v[4], u[4];
            #pragma unroll
            for (int k = 0; k < 4; k++) v[k] = p[k][lane];
            if (lane < 18) {
                #pragma unroll
                for (int k = 0; k < 4; k++) u[k] = p[k][32 + lane];
            }
            #pragma unroll
            for (int k = 0; k < 4; k++) {
                rs += e[k];
                a0.x += e[k] * v[k].x; a0.y += e[k] * v[k].y;
                a0.z += e[k] * v[k].z; a0.w += e[k] * v[k].w;
            }
            if (lane < 18) {
                #pragma unroll
                for (int k = 0; k < 4; k++) {
                    a1.x += e[k] * u[k].x; a1.y += e[k] * u[k].y;
                    a1.z += e[k] * u[k].z; a1.w += e[k] * u[k].w;
                }
            }
        }
        for (; j < cnt; j++) {
            int dst0 = __shfl_sync(0xffffffffu, rr.x, j);
            int eid0 = __shfl_sync(0xffffffffu, rr.y, j);
            float e0 = __int_as_float(__shfl_sync(0xffffffffu, rr.z, j));
            const float4* p0;
            if (role == 0) {
                p0 = (eid0 < E1C) ? (const float4*)emb1 + (size_t)eid0 * 50
                                  : (const float4*)emb2 + (size_t)(eid0 - E1C) * 50;
            } else {
                p0 = (const float4*)g_X2 + (size_t)dst0 * 50;
            }
            float4 v0 = p0[lane];
            rs += e0;
            a0.x += e0 * v0.x; a0.y += e0 * v0.y; a0.z += e0 * v0.z; a0.w += e0 * v0.w;
            if (lane < 18) {
                float4 u0 = p0[32 + lane];
                a1.x += e0 * u0.x; a1.y += e0 * u0.y; a1.z += e0 * u0.z; a1.w += e0 * u0.w;
            }
        }
    }

    float4* Out = (role == 0)
        ? (float4*)(g_accum + G_OFF)   + (size_t)node * 50
        : (float4*)(g_accum + ACC_OFF) + (size_t)node * 50;
    Out[lane] = a0;
    if (lane < 18) Out[32 + lane] = a1;
    if (role == 0 && lane == 0) g_accum[RS_OFF + node] = rs;
}

// ---- streams/events created once at load time ----
struct GraphResources {
    cudaStream_t s1, s2;
    cudaEvent_t evStart, evT, evX2, evX1, evCSR;
    GraphResources() {
        cudaStreamCreateWithFlags(&s1, cudaStreamNonBlocking);
        cudaStreamCreateWithFlags(&s2, cudaStreamNonBlocking);
        cudaEventCreateWithFlags(&evStart, cudaEventDisableTiming);
        cudaEventCreateWithFlags(&evT, cudaEventDisableTiming);
        cudaEventCreateWithFlags(&evX2, cudaEventDisableTiming);
        cudaEventCreateWithFlags(&evX1, cudaEventDisableTiming);
        cudaEventCreateWithFlags(&evCSR, cudaEventDisableTiming);
    }
};
static GraphResources g_gr;

extern "C" void kernel_launch(void* const* d_in, const int* in_sizes, int n_in,
                              void* d_out, int out_size) {
    const float* x    = (const float*)d_in[0];
    const int*   edge = (const int*)  d_in[1];
    const float* ee1  = (const float*)d_in[2];
    const int*   edg2 = (const int*)  d_in[3];
    const float* ee2  = (const float*)d_in[4];
    const float* a    = (const float*)d_in[5];
    const float* a2   = (const float*)d_in[6];
    const float* mw   = (const float*)d_in[7];
    const float* mb   = (const float*)d_in[8];
    float* out = (float*)d_out;

    cudaFuncSetAttribute(tgemm_kernel, cudaFuncAttributeMaxDynamicSharedMemorySize, SMEM_BYTES);

    int ggrid = (N_NODES + BM - 1) / BM;
    cudaStream_t s0 = 0;

    cudaEventRecord(g_gr.evStart, s0);

    // main stream: prep
    transpose_kernel<<<(75 * 4 * FDIM + 255) / 256, 256, 0, s0>>>(a);
    cudaEventRecord(g_gr.evT, s0);
    vw_kernel<<<1, 640, 0, s0>>>(a, a2, mw);
    pvec_kernel<<<N_NODES / 8, 256, 0, s0>>>(x);

    // s2: X2 first (gather dep), then X1. 4th launch = X2 tgemm (profiled).
    cudaStreamWaitEvent(g_gr.s2, g_gr.evT, 0);
    tgemm_kernel<<<ggrid, 256, SMEM_BYTES, g_gr.s2>>>(x, N_NODES, 25, 1, nullptr);  // X2 (at 200 -> jb 25)
    cudaEventRecord(g_gr.evX2, g_gr.s2);
    tgemm_kernel<<<ggrid, 256, SMEM_BYTES, g_gr.s2>>>(x, N_NODES, 0, 0, nullptr);   // X1
    cudaEventRecord(g_gr.evX1, g_gr.s2);

    // main stream: streaming scores (overlaps GEMMs)
    score_kernel<<<E_TOT / 8, 256, 0, s0>>>(edge, ee1, edg2, ee2, mb);

    // s1: CSR build
    cudaStreamWaitEvent(g_gr.s1, g_gr.evStart, 0);
    zero_deg_kernel<<<(N_NODES + 255) / 256, 256, 0, g_gr.s1>>>();
    deg_kernel<<<(E_TOT + 255) / 256, 256, 0, g_gr.s1>>>(edge, edg2);
    scan_kernel<<<1, 1024, 0, g_gr.s1>>>();
    fill_kernel<<<(E_TOT + 255) / 256, 256, 0, g_gr.s1>>>(edge, edg2);
    cudaEventRecord(g_gr.evCSR, g_gr.s1);

    // pack (needs score + CSR), gather (needs pack + X2)
    cudaStreamWaitEvent(s0, g_gr.evCSR, 0);
    pack_kernel<<<(E_TOT + 255) / 256, 256, 0, s0>>>();
    cudaStreamWaitEvent(s0, g_gr.evX2, 0);
    gather_kernel<<<(N_NODES + 3) / 4, 256, 0, s0>>>(ee1, ee2);

    cudaStreamWaitEvent(s0, g_gr.evX1, 0);
    tgemm_kernel<<<ggrid, 256, SMEM_BYTES, s0>>>(nullptr, N_NODES, 50, 2, out);  // final (at 400 -> jb 50)
}

// round 11
// speedup vs baseline: 1.1121x; 1.1121x over previous
#include <cuda_runtime.h>
#include <cuda_bf16.h>
#include <math.h>
#include <stdint.h>

#define N_NODES 50000
#define FDIM    200
#define E1C     400000
#define E2C     100000
#define E_TOT   500000
#define ALPHA   0.2f

// tensor-GEMM tiling (bf16 3x split, K pairs)
#define BM 128
#define KP_TILE 20            // k-pairs per slab (BK = 40)
#define NKB 5
#define A_STRIDE 20           // uints per A row (conflict-free: 20*lr+lc distinct mod 32)
#define B_STRIDE 200          // uints per B kp-row (8lc+lr distinct mod 32)
#define A_BUFU (BM * A_STRIDE)          // 2560 uints per plane
#define B_BUFU (KP_TILE * B_STRIDE)     // 4000 uints per plane
#define SMEM_UINTS (4 * A_BUFU + 4 * B_BUFU)   // hi/lo x double-buffer
#define SMEM_BYTES (SMEM_UINTS * 4)

// ---- device scratch ----
__device__ float g_X1[(size_t)N_NODES * FDIM];
__device__ float g_X2[(size_t)N_NODES * FDIM];
__device__ float g_ACC[(size_t)N_NODES * FDIM];
__device__ float g_rs[N_NODES];
__device__ float g_p[4 * N_NODES];
__device__ float g_v[600];
__device__ float g_w[600];
__device__ unsigned g_bqh[300 * FDIM];   // B packed pairs: [jp][n] bf16x2 hi
__device__ unsigned g_bql[300 * FDIM];
__device__ unsigned g_xqh[(size_t)N_NODES * 100];  // x packed pairs [m][kp]
__device__ unsigned g_xql[(size_t)N_NODES * 100];
__device__ unsigned g_gqh[(size_t)N_NODES * 100];  // G packed pairs
__device__ unsigned g_gql[(size_t)N_NODES * 100];
__device__ float g_ee[E_TOT];
__device__ int  g_deg[N_NODES];
__device__ int  g_off[N_NODES + 1];
__device__ int  g_cur[N_NODES];
__device__ int2 g_rec[E_TOT];
__device__ int4 g_rec3[E_TOT];

__device__ __forceinline__ float dot4(float4 a, float4 b) {
    return a.x * b.x + a.y * b.y + a.z * b.z + a.w * b.w;
}

__device__ __forceinline__ float tanh_fast(float x) {
    float y;
    asm("tanh.approx.f32 %0, %1;" : "=f"(y) : "f"(x));
    return y;
}

// split two fp32 into packed bf16x2 hi + lo
__device__ __forceinline__ void split_pack2(float f0, float f1,
                                            unsigned& hi, unsigned& lo) {
    __nv_bfloat162 h = __float22bfloat162_rn(make_float2(f0, f1));
    hi = *reinterpret_cast<unsigned*>(&h);
    float l0 = f0 - __bfloat162float(h.x);
    float l1 = f1 - __bfloat162float(h.y);
    __nv_bfloat162 l = __float22bfloat162_rn(make_float2(l0, l1));
    lo = *reinterpret_cast<unsigned*>(&l);
}

__device__ __forceinline__ void mma_bf16_k16(float* c, const unsigned* a,
                                             unsigned b0, unsigned b1) {
    asm volatile("mma.sync.aligned.m16n8k16.row.col.f32.bf16.bf16.f32 "
                 "{%0,%1,%2,%3}, {%4,%5,%6,%7}, {%8,%9}, {%0,%1,%2,%3};"
                 : "+f"(c[0]), "+f"(c[1]), "+f"(c[2]), "+f"(c[3])
                 : "r"(a[0]), "r"(a[1]), "r"(a[2]), "r"(a[3]), "r"(b0), "r"(b1));
}

__device__ __forceinline__ void mma_bf16_k8(float* c, unsigned a0, unsigned a1,
                                            unsigned b0) {
    asm volatile("mma.sync.aligned.m16n8k8.row.col.f32.bf16.bf16.f32 "
                 "{%0,%1,%2,%3}, {%4,%5}, {%6}, {%0,%1,%2,%3};"
                 : "+f"(c[0]), "+f"(c[1]), "+f"(c[2]), "+f"(c[3])
                 : "r"(a0), "r"(a1), "r"(b0));
}

__device__ __forceinline__ void cp_async16(void* smem_dst, const void* gmem_src, bool pred) {
    uint32_t s = (uint32_t)__cvta_generic_to_shared(smem_dst);
    int sz = pred ? 16 : 0;
    asm volatile("cp.async.cg.shared.global [%0], [%1], 16, %2;"
                 :: "r"(s), "l"(gmem_src), "r"(sz));
}
__device__ __forceinline__ void cp_commit() {
    asm volatile("cp.async.commit_group;");
}
template<int N>
__device__ __forceinline__ void cp_wait() {
    asm volatile("cp.async.wait_group %0;" :: "n"(N));
}

// ---------------- CSR build ----------------
__global__ __launch_bounds__(256) void zero_deg_kernel() {
    int i = blockIdx.x * blockDim.x + threadIdx.x;
    if (i < N_NODES) g_deg[i] = 0;
}

__global__ __launch_bounds__(256) void deg_kernel(const int* __restrict__ edge,
                                                  const int* __restrict__ edge2) {
    int e = blockIdx.x * blockDim.x + threadIdx.x;
    if (e >= E_TOT) return;
    int src = (e < E1C) ? edge[e] : edge2[e - E1C];
    atomicAdd(&g_deg[src], 1);
}

__global__ __launch_bounds__(1024) void scan_kernel() {
    __shared__ int warp_sums[32];
    __shared__ int s_total;
    __shared__ int s_run;
    int t = threadIdx.x;
    int lane = t & 31, wid = t >> 5;
    if (t == 0) s_run = 0;
    __syncthreads();
    for (int base = 0; base < N_NODES; base += 1024) {
        int idx = base + t;
        int v = (idx < N_NODES) ? g_deg[idx] : 0;
        int incl = v;
        #pragma unroll
        for (int d = 1; d < 32; d <<= 1) {
            int n = __shfl_up_sync(0xffffffffu, incl, d);
            if (lane >= d) incl += n;
        }
        if (lane == 31) warp_sums[wid] = incl;
        __syncthreads();
        if (wid == 0) {
            int ws = warp_sums[lane];
            int wincl = ws;
            #pragma unroll
            for (int d = 1; d < 32; d <<= 1) {
                int n = __shfl_up_sync(0xffffffffu, wincl, d);
                if (lane >= d) wincl += n;
            }
            warp_sums[lane] = wincl - ws;
            if (lane == 31) s_total = wincl;
        }
        __syncthreads();
        int excl = s_run + warp_sums[wid] + incl - v;
        if (idx < N_NODES) { g_off[idx] = excl; g_cur[idx] = excl; }
        __syncthreads();
        if (t == 0) s_run += s_total;
        __syncthreads();
    }
    if (t == 0) g_off[N_NODES] = s_run;
}

__global__ __launch_bounds__(256) void fill_kernel(const int* __restrict__ edge,
                                                   const int* __restrict__ edge2) {
    int e = blockIdx.x * blockDim.x + threadIdx.x;
    if (e >= E_TOT) return;
    int src, dst;
    if (e < E1C) { src = edge[e]; dst = edge[E1C + e]; }
    else         { src = edge2[e - E1C]; dst = edge2[E2C + (e - E1C)]; }
    int pos = atomicAdd(&g_cur[src], 1);
    g_rec[pos] = make_int2(dst, e);
}

__global__ __launch_bounds__(256) void pack_kernel() {
    int i = blockIdx.x * blockDim.x + threadIdx.x;
    if (i >= E_TOT) return;
    int2 r = g_rec[i];
    float e = g_ee[r.y];
    g_rec3[i] = make_int4(r.x, r.y, __float_as_int(e), 0);
}

// ---------------- weights prep: B packed bf16 hi/lo pairs ----------------
__global__ __launch_bounds__(256) void transpose_kernel(const float* __restrict__ a) {
    int i = blockIdx.x * blockDim.x + threadIdx.x;
    if (i >= 300 * FDIM) return;
    int jp = i / FDIM;
    int n  = i % FDIM;
    float f0 = a[n * 600 + 2 * jp];
    float f1 = a[n * 600 + 2 * jp + 1];
    unsigned hi, lo;
    split_pack2(f0, f1, hi, lo);
    g_bqh[i] = hi;
    g_bql[i] = lo;
}

// ---------------- pack x into bf16 hi/lo pairs ----------------
__global__ __launch_bounds__(256) void pack_x_kernel(const float* __restrict__ x) {
    int i = blockIdx.x * blockDim.x + threadIdx.x;
    if (i >= N_NODES * 50) return;
    int m = i / 50, c = i % 50;
    float4 v = ((const float4*)x)[i];
    unsigned h0, l0, h1, l1;
    split_pack2(v.x, v.y, h0, l0);
    split_pack2(v.z, v.w, h1, l1);
    size_t o = (size_t)m * 100 + 2 * c;
    *(uint2*)&g_xqh[o] = make_uint2(h0, h1);
    *(uint2*)&g_xql[o] = make_uint2(l0, l1);
}

__global__ __launch_bounds__(640) void vw_kernel(const float* __restrict__ a,
                                                 const float* __restrict__ a2,
                                                 const float* __restrict__ mw) {
    int j = threadIdx.x;
    if (j >= 600) return;
    float v = 0.f, w = 0.f;
    for (int o = 0; o < FDIM; o++) {
        float aj = a[o * 600 + j];
        v += aj * a2[o];
        w += aj * mw[o];
    }
    g_v[j] = v;
    g_w[j] = w;
}

__global__ __launch_bounds__(256) void pvec_kernel(const float* __restrict__ x) {
    __shared__ float4 sv[100];
    __shared__ float4 sw[100];
    int t = threadIdx.x;
    if (t < 100)       sv[t]       = ((const float4*)g_v)[t];
    else if (t < 200)  sw[t - 100] = ((const float4*)g_w)[t - 100];
    __syncthreads();

    int warp = t >> 5, lane = t & 31;
    int node = blockIdx.x * 8 + warp;
    if (node >= N_NODES) return;

    const float4* xr = (const float4*)x + (size_t)node * 50;
    float4 x0 = xr[lane];
    float4 x1 = (lane < 18) ? xr[32 + lane] : make_float4(0, 0, 0, 0);

    float p1  = dot4(x0, sv[lane])      + ((lane < 18) ? dot4(x1, sv[32 + lane]) : 0.f);
    float p2  = dot4(x0, sv[50 + lane]) + ((lane < 18) ? dot4(x1, sv[82 + lane]) : 0.f);
    float pm1 = dot4(x0, sw[lane])      + ((lane < 18) ? dot4(x1, sw[32 + lane]) : 0.f);
    float pm2 = dot4(x0, sw[50 + lane]) + ((lane < 18) ? dot4(x1, sw[82 + lane]) : 0.f);

    #pragma unroll
    for (int off = 16; off; off >>= 1) {
        p1  += __shfl_xor_sync(0xffffffffu, p1, off);
        p2  += __shfl_xor_sync(0xffffffffu, p2, off);
        pm1 += __shfl_xor_sync(0xffffffffu, pm1, off);
        pm2 += __shfl_xor_sync(0xffffffffu, pm2, off);
    }
    if (lane == 0) {
        g_p[node]               = p1;
        g_p[N_NODES + node]     = p2;
        g_p[2 * N_NODES + node] = pm1;
        g_p[3 * N_NODES + node] = pm2;
    }
}

// ---------------- bf16 3x tensor-core GEMM ----------------
__device__ __forceinline__ void stage_tile(unsigned* Ah, unsigned* Al,
                                           unsigned* Bh, unsigned* Bl,
                                           const unsigned* gAh, const unsigned* gAl,
                                           int M, int row0, int jp0, int kb, int t) {
    int kp0 = kb * KP_TILE;
    // A: 128 rows x 20 uints per plane = 640 float4 per plane
    #pragma unroll
    for (int i = 0; i < 3; i++) {
        int idx = t + i * 256;
        if (idx < 640) {
            int r = idx / 5, c4 = idx % 5;
            bool ok = (row0 + r) < M;
            size_t go = (size_t)(row0 + r) * 100 + kp0 + c4 * 4;
            cp_async16(Ah + r * A_STRIDE + c4 * 4, gAh + go, ok);
            cp_async16(Al + r * A_STRIDE + c4 * 4, gAl + go, ok);
        }
    }
    // B: 20 kp-rows x 200 = 4000 uints = 1000 float4 per plane (contiguous global)
    const unsigned* sH = g_bqh + (size_t)(jp0 + kp0) * FDIM;
    const unsigned* sL = g_bql + (size_t)(jp0 + kp0) * FDIM;
    #pragma unroll
    for (int i = 0; i < 4; i++) {
        int idx = t + i * 256;
        if (idx < 1000) {
            cp_async16(Bh + idx * 4, sH + idx * 4, true);
            cp_async16(Bl + idx * 4, sL + idx * 4, true);
        }
    }
}

// dest 0 -> g_X1, 1 -> g_X2, 2 -> final epilogue into fout
__global__ void __launch_bounds__(256, 1)
tgemm_kernel(const unsigned* __restrict__ gAh, const unsigned* __restrict__ gAl,
             int M, int jp0, int dest, float* __restrict__ fout) {
    extern __shared__ unsigned smu_[];
    unsigned* Ah[2] = { smu_, smu_ + A_BUFU };
    unsigned* Al[2] = { smu_ + 2 * A_BUFU, smu_ + 3 * A_BUFU };
    unsigned* Bh[2] = { smu_ + 4 * A_BUFU, smu_ + 4 * A_BUFU + B_BUFU };
    unsigned* Bl[2] = { smu_ + 4 * A_BUFU + 2 * B_BUFU, smu_ + 4 * A_BUFU + 3 * B_BUFU };

    int row0 = blockIdx.x * BM;
    int t = threadIdx.x;
    int warp = t >> 5, lane = t & 31;
    int mg = warp >> 1;
    int ng = warp & 1;
    int n0 = ng * 96;
    int m0w = mg * 32;
    int lr = lane >> 2;
    int lc = lane & 3;

    float acc[2][13][4];
    #pragma unroll
    for (int a_ = 0; a_ < 2; a_++)
        #pragma unroll
        for (int b_ = 0; b_ < 13; b_++)
            #pragma unroll
            for (int c_ = 0; c_ < 4; c_++) acc[a_][b_][c_] = 0.f;

    stage_tile(Ah[0], Al[0], Bh[0], Bl[0], gAh, gAl, M, row0, jp0, 0, t);
    cp_commit();

    for (int kb = 0; kb < NKB; kb++) {
        int cur = kb & 1;
        if (kb + 1 < NKB) {
            stage_tile(Ah[cur ^ 1], Al[cur ^ 1], Bh[cur ^ 1], Bl[cur ^ 1],
                       gAh, gAl, M, row0, jp0, kb + 1, t);
            cp_commit();
            cp_wait<1>();
        } else {
            cp_wait<0>();
        }
        __syncthreads();

        const unsigned* Ach = Ah[cur];
        const unsigned* Acl = Al[cur];
        const unsigned* Bch = Bh[cur];
        const unsigned* Bcl = Bl[cur];

        // two k16 steps (pairs 0..7, 8..15)
        #pragma unroll
        for (int st = 0; st < 2; st++) {
            int kpb = st * 8;
            unsigned ah[2][4], al[2][4];
            #pragma unroll
            for (int mt = 0; mt < 2; mt++) {
                int mrow = m0w + mt * 16 + lr;
                ah[mt][0] = Ach[mrow * A_STRIDE + kpb + lc];
                ah[mt][1] = Ach[(mrow + 8) * A_STRIDE + kpb + lc];
                ah[mt][2] = Ach[mrow * A_STRIDE + kpb + lc + 4];
                ah[mt][3] = Ach[(mrow + 8) * A_STRIDE + kpb + lc + 4];
                al[mt][0] = Acl[mrow * A_STRIDE + kpb + lc];
                al[mt][1] = Acl[(mrow + 8) * A_STRIDE + kpb + lc];
                al[mt][2] = Acl[mrow * A_STRIDE + kpb + lc + 4];
                al[mt][3] = Acl[(mrow + 8) * A_STRIDE + kpb + lc + 4];
            }
            #pragma unroll
            for (int nt = 0; nt < 13; nt++) {
                int nc = n0 + nt * 8 + lr;
                unsigned bh0 = Bch[(kpb + lc) * B_STRIDE + nc];
                unsigned bh1 = Bch[(kpb + lc + 4) * B_STRIDE + nc];
                unsigned bl0 = Bcl[(kpb + lc) * B_STRIDE + nc];
                unsigned bl1 = Bcl[(kpb + lc + 4) * B_STRIDE + nc];
                #pragma unroll
                for (int mt = 0; mt < 2; mt++) {
                    mma_bf16_k16(acc[mt][nt], ah[mt], bh0, bh1);
                    mma_bf16_k16(acc[mt][nt], ah[mt], bl0, bl1);
                    mma_bf16_k16(acc[mt][nt], al[mt], bh0, bh1);
                }
            }
        }
        // k8 tail (pairs 16..19)
        {
            unsigned ah8[2][2], al8[2][2];
            #pragma unroll
            for (int mt = 0; mt < 2; mt++) {
                int mrow = m0w + mt * 16 + lr;
                ah8[mt][0] = Ach[mrow * A_STRIDE + 16 + lc];
                ah8[mt][1] = Ach[(mrow + 8) * A_STRIDE + 16 + lc];
                al8[mt][0] = Acl[mrow * A_STRIDE + 16 + lc];
                al8[mt][1] = Acl[(mrow + 8) * A_STRIDE + 16 + lc];
            }
            #pragma unroll
            for (int nt = 0; nt < 13; nt++) {
                int nc = n0 + nt * 8 + lr;
                unsigned bh0 = Bch[(16 + lc) * B_STRIDE + nc];
                unsigned bl0 = Bcl[(16 + lc) * B_STRIDE + nc];
                #pragma unroll
                for (int mt = 0; mt < 2; mt++) {
                    mma_bf16_k8(acc[mt][nt], ah8[mt][0], ah8[mt][1], bh0);
                    mma_bf16_k8(acc[mt][nt], ah8[mt][0], ah8[mt][1], bl0);
                    mma_bf16_k8(acc[mt][nt], al8[mt][0], al8[mt][1], bh0);
                }
            }
        }
        __syncthreads();
    }

    if (dest != 2) {
        float* Out = (dest == 0) ? g_X1 : g_X2;
        #pragma unroll
        for (int mt = 0; mt < 2; mt++) {
            int r0 = row0 + m0w + mt * 16 + lr;
            #pragma unroll
            for (int nt = 0; nt < 13; nt++) {
                int col = n0 + nt * 8 + 2 * lc;
                if (r0 < M)
                    *(float2*)(Out + (size_t)r0 * FDIM + col) =
                        make_float2(acc[mt][nt][0], acc[mt][nt][1]);
                if (r0 + 8 < M)
                    *(float2*)(Out + (size_t)(r0 + 8) * FDIM + col) =
                        make_float2(acc[mt][nt][2], acc[mt][nt][3]);
            }
        }
    } else {
        #pragma unroll
        for (int mt = 0; mt < 2; mt++) {
            #pragma unroll
            for (int h = 0; h < 2; h++) {
                int r = row0 + m0w + mt * 16 + lr + 8 * h;
                if (r >= M) continue;
                float rs = g_rs[r];
                if (rs == 0.f) {
                    #pragma unroll
                    for (int nt = 0; nt < 13; nt++) {
                        int col = n0 + nt * 8 + 2 * lc;
                        *(float2*)(fout + (size_t)r * FDIM + col) = make_float2(0.f, 0.f);
                    }
                } else {
                    float inv = 1.f / rs;
                    #pragma unroll
                    for (int nt = 0; nt < 13; nt++) {
                        int col = n0 + nt * 8 + 2 * lc;
                        size_t idx = (size_t)r * FDIM + col;
                        float2 x1 = *(const float2*)(g_X1 + idx);
                        float2 av = *(const float2*)(g_ACC + idx);
                        float g0 = acc[mt][nt][2 * h + 0];
                        float g1 = acc[mt][nt][2 * h + 1];
                        float v0 = x1.x + (av.x + g0) * inv;
                        float v1 = x1.y + (av.y + g1) * inv;
                        v0 = (v0 > 0.f) ? v0 : (expf(v0) - 1.f);
                        v1 = (v1 > 0.f) ? v1 : (expf(v1) - 1.f);
                        *(float2*)(fout + idx) = make_float2(v0, v1);
                    }
                }
            }
        }
    }
}

// ---------------- phase 1: streaming edge scores ----------------
__global__ __launch_bounds__(256) void score_kernel(const int* __restrict__ edge,
                                                    const float* __restrict__ emb1,
                                                    const int* __restrict__ edge2,
                                                    const float* __restrict__ emb2,
                                                    const float* __restrict__ mlp_b) {
    __shared__ float4 sv[50];
    __shared__ float4 sw[50];
    int t = threadIdx.x;
    if (t < 50)       sv[t]      = *(const float4*)&g_v[400 + t * 4];
    else if (t < 100) sw[t - 50] = *(const float4*)&g_w[400 + (t - 50) * 4];
    __syncthreads();

    int warp = t >> 5, lane = t & 31;
    int eid = blockIdx.x * 8 + warp;
    if (eid >= E_TOT) return;

    int src, dst;
    const float4* emb;
    if (eid < E1C) {
        src = edge[eid];
        dst = edge[E1C + eid];
        emb = (const float4*)emb1 + (size_t)eid * 50;
    } else {
        int e2 = eid - E1C;
        src = edge2[e2];
        dst = edge2[E2C + e2];
        emb = (const float4*)emb2 + (size_t)e2 * 50;
    }

    float4 m0 = emb[lane];
    float4 m1 = (lane < 18) ? emb[32 + lane] : make_float4(0, 0, 0, 0);

    float q3 = dot4(m0, sv[lane]) + ((lane < 18) ? dot4(m1, sv[32 + lane]) : 0.f);
    float qm = dot4(m0, sw[lane]) + ((lane < 18) ? dot4(m1, sw[32 + lane]) : 0.f);
    #pragma unroll
    for (int off = 16; off; off >>= 1) {
        q3 += __shfl_xor_sync(0xffffffffu, q3, off);
        qm += __shfl_xor_sync(0xffffffffu, qm, off);
    }

    if (lane == 0) {
        float sa = g_p[src] + g_p[N_NODES + dst] + q3;
        float sm = g_p[2 * N_NODES + src] + g_p[3 * N_NODES + dst] + qm + mlp_b[0];
        float lrv = (sa > 0.f) ? sa : ALPHA * sa;
        float pw = -lrv * tanh_fast(sm) * (1.0f / (float)E_TOT);
        g_ee[eid] = __expf(pw);
    }
}

// ---------------- phase 2: role-split gather (G written packed bf16) ----------------
__global__ __launch_bounds__(256) void gather_kernel(const float* __restrict__ emb1,
                                                     const float* __restrict__ emb2) {
    int t = threadIdx.x;
    int warp = t >> 5, lane = t & 31;
    int node = blockIdx.x * 4 + (warp >> 1);
    int role = warp & 1;
    if (node >= N_NODES) return;

    int beg = g_off[node];
    int end = g_off[node + 1];

    float4 a0 = make_float4(0, 0, 0, 0), a1 = a0;
    float rs = 0.f;

    for (int base = beg; base < end; base += 32) {
        int cnt = min(32, end - base);
        int4 rr = (lane < cnt) ? g_rec3[base + lane] : make_int4(0, 0, 0, 0);

        int j = 0;
        for (; j + 4 <= cnt; j += 4) {
            const float4* p[4];
            float e[4];
            #pragma unroll
            for (int k = 0; k < 4; k++) {
                int dstk = __shfl_sync(0xffffffffu, rr.x, j + k);
                int eidk = __shfl_sync(0xffffffffu, rr.y, j + k);
                e[k] = __int_as_float(__shfl_sync(0xffffffffu, rr.z, j + k));
                if (role == 0) {
                    p[k] = (eidk < E1C) ? (const float4*)emb1 + (size_t)eidk * 50
                                        : (const float4*)emb2 + (size_t)(eidk - E1C) * 50;
                } else {
                    p[k] = (const float4*)g_X2 + (size_t)dstk * 50;
                }
            }
            float4 v[4], u[4];
            #pragma unroll
            for (int k = 0; k < 4; k++) v[k] = p[k][lane];
            if (lane < 18) {
                #pragma unroll
                for (int k = 0; k < 4; k++) u[k] = p[k][32 + lane];
            }
            #pragma unroll
            for (int k = 0; k < 4; k++) {
                rs += e[k];
                a0.x += e[k] * v[k].x; a0.y += e[k] * v[k].y;
                a0.z += e[k] * v[k].z; a0.w += e[k] * v[k].w;
            }
            if (lane < 18) {
                #pragma unroll
                for (int k = 0; k < 4; k++) {
                    a1.x += e[k] * u[k].x; a1.y += e[k] * u[k].y;
                    a1.z += e[k] * u[k].z; a1.w += e[k] * u[k].w;
                }
            }
        }
        for (; j < cnt; j++) {
            int dst0 = __shfl_sync(0xffffffffu, rr.x, j);
            int eid0 = __shfl_sync(0xffffffffu, rr.y, j);
            float e0 = __int_as_float(__shfl_sync(0xffffffffu, rr.z, j));
            const float4* p0;
            if (role == 0) {
                p0 = (eid0 < E1C) ? (const float4*)emb1 + (size_t)eid0 * 50
                                  : (const float4*)emb2 + (size_t)(eid0 - E1C) * 50;
            } else {
                p0 = (const float4*)g_X2 + (size_t)dst0 * 50;
            }
            float4 v0 = p0[lane];
            rs += e0;
            a0.x += e0 * v0.x; a0.y += e0 * v0.y; a0.z += e0 * v0.z; a0.w += e0 * v0.w;
            if (lane < 18) {
                float4 u0 = p0[32 + lane];
                a1.x += e0 * u0.x; a1.y += e0 * u0.y; a1.z += e0 * u0.z; a1.w += e0 * u0.w;
            }
        }
    }

    if (role == 0) {
        // G -> packed bf16 hi/lo pairs for the final GEMM
        unsigned h0, l0, h1, l1;
        split_pack2(a0.x, a0.y, h0, l0);
        split_pack2(a0.z, a0.w, h1, l1);
        size_t o = (size_t)node * 100 + 2 * lane;
        *(uint2*)&g_gqh[o] = make_uint2(h0, h1);
        *(uint2*)&g_gql[o] = make_uint2(l0, l1);
        if (lane < 18) {
            split_pack2(a1.x, a1.y, h0, l0);
            split_pack2(a1.z, a1.w, h1, l1);
            size_t o2 = (size_t)node * 100 + 64 + 2 * lane;
            *(uint2*)&g_gqh[o2] = make_uint2(h0, h1);
            *(uint2*)&g_gql[o2] = make_uint2(l0, l1);
        }
        if (lane == 0) g_rs[node] = rs;
    } else {
        float4* Out = (float4*)g_ACC + (size_t)node * 50;
        Out[lane] = a0;
        if (lane < 18) Out[32 + lane] = a1;
    }
}

// ---- streams/events created once at load time ----
struct GraphResources {
    cudaStream_t s1, s2;
    cudaEvent_t evStart, evT, evX2, evX1, evCSR;
    GraphResources() {
        cudaStreamCreateWithFlags(&s1, cudaStreamNonBlocking);
        cudaStreamCreateWithFlags(&s2, cudaStreamNonBlocking);
        cudaEventCreateWithFlags(&evStart, cudaEventDisableTiming);
        cudaEventCreateWithFlags(&evT, cudaEventDisableTiming);
        cudaEventCreateWithFlags(&evX2, cudaEventDisableTiming);
        cudaEventCreateWithFlags(&evX1, cudaEventDisableTiming);
        cudaEventCreateWithFlags(&evCSR, cudaEventDisableTiming);
    }
};
static GraphResources g_gr;

extern "C" void kernel_launch(void* const* d_in, const int* in_sizes, int n_in,
                              void* d_out, int out_size) {
    const float* x    = (const float*)d_in[0];
    const int*   edge = (const int*)  d_in[1];
    const float* ee1  = (const float*)d_in[2];
    const int*   edg2 = (const int*)  d_in[3];
    const float* ee2  = (const float*)d_in[4];
    const float* a    = (const float*)d_in[5];
    const float* a2   = (const float*)d_in[6];
    const float* mw   = (const float*)d_in[7];
    const float* mb   = (const float*)d_in[8];
    float* out = (float*)d_out;

    cudaFuncSetAttribute(tgemm_kernel, cudaFuncAttributeMaxDynamicSharedMemorySize, SMEM_BYTES);

    int ggrid = (N_NODES + BM - 1) / BM;
    cudaStream_t s0 = 0;

    // device-symbol addresses for A operands
    unsigned *xqh_p, *xql_p, *gqh_p, *gql_p;
    cudaGetSymbolAddress((void**)&xqh_p, g_xqh);
    cudaGetSymbolAddress((void**)&xql_p, g_xql);
    cudaGetSymbolAddress((void**)&gqh_p, g_gqh);
    cudaGetSymbolAddress((void**)&gql_p, g_gql);

    cudaEventRecord(g_gr.evStart, s0);

    // main stream: prep (launches 1-3), then GEMMs on s2 (4th launch = X2 tgemm)
    transpose_kernel<<<(300 * FDIM + 255) / 256, 256, 0, s0>>>(a);
    vw_kernel<<<1, 640, 0, s0>>>(a, a2, mw);
    pack_x_kernel<<<(N_NODES * 50 + 255) / 256, 256, 0, s0>>>(x);
    cudaEventRecord(g_gr.evT, s0);

    cudaStreamWaitEvent(g_gr.s2, g_gr.evT, 0);
    tgemm_kernel<<<ggrid, 256, SMEM_BYTES, g_gr.s2>>>(xqh_p, xql_p, N_NODES, 100, 1, nullptr);  // X2
    cudaEventRecord(g_gr.evX2, g_gr.s2);
    tgemm_kernel<<<ggrid, 256, SMEM_BYTES, g_gr.s2>>>(xqh_p, xql_p, N_NODES, 0, 0, nullptr);    // X1
    cudaEventRecord(g_gr.evX1, g_gr.s2);

    // main stream: pvec + streaming scores (overlaps GEMMs)
    pvec_kernel<<<N_NODES / 8, 256, 0, s0>>>(x);
    score_kernel<<<E_TOT / 8, 256, 0, s0>>>(edge, ee1, edg2, ee2, mb);

    // s1: CSR build
    cudaStreamWaitEvent(g_gr.s1, g_gr.evStart, 0);
    zero_deg_kernel<<<(N_NODES + 255) / 256, 256, 0, g_gr.s1>>>();
    deg_kernel<<<(E_TOT + 255) / 256, 256, 0, g_gr.s1>>>(edge, edg2);
    scan_kernel<<<1, 1024, 0, g_gr.s1>>>();
    fill_kernel<<<(E_TOT + 255) / 256, 256, 0, g_gr.s1>>>(edge, edg2);
    cudaEventRecord(g_gr.evCSR, g_gr.s1);

    // pack recs (needs score + CSR), gather (needs pack + X2)
    cudaStreamWaitEvent(s0, g_gr.evCSR, 0);
    pack_kernel<<<(E_TOT + 255) / 256, 256, 0, s0>>>();
    cudaStreamWaitEvent(s0, g_gr.evX2, 0);
    gather_kernel<<<(N_NODES + 3) / 4, 256, 0, s0>>>(ee1, ee2);

    cudaStreamWaitEvent(s0, g_gr.evX1, 0);
    tgemm_kernel<<<ggrid, 256, SMEM_BYTES, s0>>>(gqh_p, gql_p, N_NODES, 200, 2, out);  // final
}

// round 12
// speedup vs baseline: 1.1915x; 1.0714x over previous
#include <cuda_runtime.h>
#include <cuda_bf16.h>
#include <math.h>
#include <stdint.h>

#define N_NODES 50000
#define FDIM    200
#define E1C     400000
#define E2C     100000
#define E_TOT   500000
#define ALPHA   0.2f

// tensor-GEMM tiling (bf16 3x split, K pairs), 512 threads / 16 warps
#define BM 128
#define KP_TILE 20
#define NKB 5
#define A_STRIDE 20
#define B_STRIDE 200
#define A_BUFU (BM * A_STRIDE)              // 2560 uints per plane
#define B_BUFU (KP_TILE * B_STRIDE + 64)    // +pad for overlapped n-group reads
#define SMEM_UINTS (4 * A_BUFU + 4 * B_BUFU)
#define SMEM_BYTES (SMEM_UINTS * 4)
#define TG_THREADS 512

// ---- device scratch ----
__device__ float g_X1[(size_t)N_NODES * FDIM];
__device__ float g_X2[(size_t)N_NODES * FDIM];
__device__ float g_ACC[(size_t)N_NODES * FDIM];
__device__ float g_rs[N_NODES];
__device__ float g_p[4 * N_NODES];
__device__ float g_v[600];
__device__ float g_w[600];
__device__ unsigned g_bqh[300 * FDIM];
__device__ unsigned g_bql[300 * FDIM];
__device__ unsigned g_xqh[(size_t)N_NODES * 100];
__device__ unsigned g_xql[(size_t)N_NODES * 100];
__device__ unsigned g_gqh[(size_t)N_NODES * 100];
__device__ unsigned g_gql[(size_t)N_NODES * 100];
__device__ float g_ee[E_TOT];
__device__ int  g_deg[N_NODES];
__device__ int  g_off[N_NODES + 1];
__device__ int  g_cur[N_NODES];
__device__ int2 g_rec[E_TOT];
__device__ int4 g_rec3[E_TOT];

__device__ __forceinline__ float dot4(float4 a, float4 b) {
    return a.x * b.x + a.y * b.y + a.z * b.z + a.w * b.w;
}

__device__ __forceinline__ float tanh_fast(float x) {
    float y;
    asm("tanh.approx.f32 %0, %1;" : "=f"(y) : "f"(x));
    return y;
}

__device__ __forceinline__ void split_pack2(float f0, float f1,
                                            unsigned& hi, unsigned& lo) {
    __nv_bfloat162 h = __float22bfloat162_rn(make_float2(f0, f1));
    hi = *reinterpret_cast<unsigned*>(&h);
    float l0 = f0 - __bfloat162float(h.x);
    float l1 = f1 - __bfloat162float(h.y);
    __nv_bfloat162 l = __float22bfloat162_rn(make_float2(l0, l1));
    lo = *reinterpret_cast<unsigned*>(&l);
}

__device__ __forceinline__ void mma_bf16_k16(float* c, const unsigned* a,
                                             unsigned b0, unsigned b1) {
    asm volatile("mma.sync.aligned.m16n8k16.row.col.f32.bf16.bf16.f32 "
                 "{%0,%1,%2,%3}, {%4,%5,%6,%7}, {%8,%9}, {%0,%1,%2,%3};"
                 : "+f"(c[0]), "+f"(c[1]), "+f"(c[2]), "+f"(c[3])
                 : "r"(a[0]), "r"(a[1]), "r"(a[2]), "r"(a[3]), "r"(b0), "r"(b1));
}

__device__ __forceinline__ void mma_bf16_k8(float* c, unsigned a0, unsigned a1,
                                            unsigned b0) {
    asm volatile("mma.sync.aligned.m16n8k8.row.col.f32.bf16.bf16.f32 "
                 "{%0,%1,%2,%3}, {%4,%5}, {%6}, {%0,%1,%2,%3};"
                 : "+f"(c[0]), "+f"(c[1]), "+f"(c[2]), "+f"(c[3])
                 : "r"(a0), "r"(a1), "r"(b0));
}

__device__ __forceinline__ void cp_async16(void* smem_dst, const void* gmem_src, bool pred) {
    uint32_t s = (uint32_t)__cvta_generic_to_shared(smem_dst);
    int sz = pred ? 16 : 0;
    asm volatile("cp.async.cg.shared.global [%0], [%1], 16, %2;"
                 :: "r"(s), "l"(gmem_src), "r"(sz));
}
__device__ __forceinline__ void cp_commit() {
    asm volatile("cp.async.commit_group;");
}
template<int N>
__device__ __forceinline__ void cp_wait() {
    asm volatile("cp.async.wait_group %0;" :: "n"(N));
}

// ---------------- CSR build ----------------
__global__ __launch_bounds__(256) void zero_deg_kernel() {
    int i = blockIdx.x * blockDim.x + threadIdx.x;
    if (i < N_NODES) g_deg[i] = 0;
}

__global__ __launch_bounds__(256) void deg_kernel(const int* __restrict__ edge,
                                                  const int* __restrict__ edge2) {
    int e = blockIdx.x * blockDim.x + threadIdx.x;
    if (e >= E_TOT) return;
    int src = (e < E1C) ? edge[e] : edge2[e - E1C];
    atomicAdd(&g_deg[src], 1);
}

__global__ __launch_bounds__(1024) void scan_kernel() {
    __shared__ int warp_sums[32];
    __shared__ int s_total;
    __shared__ int s_run;
    int t = threadIdx.x;
    int lane = t & 31, wid = t >> 5;
    if (t == 0) s_run = 0;
    __syncthreads();
    for (int base = 0; base < N_NODES; base += 1024) {
        int idx = base + t;
        int v = (idx < N_NODES) ? g_deg[idx] : 0;
        int incl = v;
        #pragma unroll
        for (int d = 1; d < 32; d <<= 1) {
            int n = __shfl_up_sync(0xffffffffu, incl, d);
            if (lane >= d) incl += n;
        }
        if (lane == 31) warp_sums[wid] = incl;
        __syncthreads();
        if (wid == 0) {
            int ws = warp_sums[lane];
            int wincl = ws;
            #pragma unroll
            for (int d = 1; d < 32; d <<= 1) {
                int n = __shfl_up_sync(0xffffffffu, wincl, d);
                if (lane >= d) wincl += n;
            }
            warp_sums[lane] = wincl - ws;
            if (lane == 31) s_total = wincl;
        }
        __syncthreads();
        int excl = s_run + warp_sums[wid] + incl - v;
        if (idx < N_NODES) { g_off[idx] = excl; g_cur[idx] = excl; }
        __syncthreads();
        if (t == 0) s_run += s_total;
        __syncthreads();
    }
    if (t == 0) g_off[N_NODES] = s_run;
}

__global__ __launch_bounds__(256) void fill_kernel(const int* __restrict__ edge,
                                                   const int* __restrict__ edge2) {
    int e = blockIdx.x * blockDim.x + threadIdx.x;
    if (e >= E_TOT) return;
    int src, dst;
    if (e < E1C) { src = edge[e]; dst = edge[E1C + e]; }
    else         { src = edge2[e - E1C]; dst = edge2[E2C + (e - E1C)]; }
    int pos = atomicAdd(&g_cur[src], 1);
    g_rec[pos] = make_int2(dst, e);
}

__global__ __launch_bounds__(256) void pack_kernel() {
    int i = blockIdx.x * blockDim.x + threadIdx.x;
    if (i >= E_TOT) return;
    int2 r = g_rec[i];
    float e = g_ee[r.y];
    g_rec3[i] = make_int4(r.x, r.y, __float_as_int(e), 0);
}

// ---------------- weights prep ----------------
__global__ __launch_bounds__(256) void transpose_kernel(const float* __restrict__ a) {
    int i = blockIdx.x * blockDim.x + threadIdx.x;
    if (i >= 300 * FDIM) return;
    int jp = i / FDIM;
    int n  = i % FDIM;
    float f0 = a[n * 600 + 2 * jp];
    float f1 = a[n * 600 + 2 * jp + 1];
    unsigned hi, lo;
    split_pack2(f0, f1, hi, lo);
    g_bqh[i] = hi;
    g_bql[i] = lo;
}

__global__ __launch_bounds__(256) void pack_x_kernel(const float* __restrict__ x) {
    int i = blockIdx.x * blockDim.x + threadIdx.x;
    if (i >= N_NODES * 50) return;
    int m = i / 50, c = i % 50;
    float4 v = ((const float4*)x)[i];
    unsigned h0, l0, h1, l1;
    split_pack2(v.x, v.y, h0, l0);
    split_pack2(v.z, v.w, h1, l1);
    size_t o = (size_t)m * 100 + 2 * c;
    *(uint2*)&g_xqh[o] = make_uint2(h0, h1);
    *(uint2*)&g_xql[o] = make_uint2(l0, l1);
}

__global__ __launch_bounds__(640) void vw_kernel(const float* __restrict__ a,
                                                 const float* __restrict__ a2,
                                                 const float* __restrict__ mw) {
    int j = threadIdx.x;
    if (j >= 600) return;
    float v = 0.f, w = 0.f;
    for (int o = 0; o < FDIM; o++) {
        float aj = a[o * 600 + j];
        v += aj * a2[o];
        w += aj * mw[o];
    }
    g_v[j] = v;
    g_w[j] = w;
}

__global__ __launch_bounds__(256) void pvec_kernel(const float* __restrict__ x) {
    __shared__ float4 sv[100];
    __shared__ float4 sw[100];
    int t = threadIdx.x;
    if (t < 100)       sv[t]       = ((const float4*)g_v)[t];
    else if (t < 200)  sw[t - 100] = ((const float4*)g_w)[t - 100];
    __syncthreads();

    int warp = t >> 5, lane = t & 31;
    int node = blockIdx.x * 8 + warp;
    if (node >= N_NODES) return;

    const float4* xr = (const float4*)x + (size_t)node * 50;
    float4 x0 = xr[lane];
    float4 x1 = (lane < 18) ? xr[32 + lane] : make_float4(0, 0, 0, 0);

    float p1  = dot4(x0, sv[lane])      + ((lane < 18) ? dot4(x1, sv[32 + lane]) : 0.f);
    float p2  = dot4(x0, sv[50 + lane]) + ((lane < 18) ? dot4(x1, sv[82 + lane]) : 0.f);
    float pm1 = dot4(x0, sw[lane])      + ((lane < 18) ? dot4(x1, sw[32 + lane]) : 0.f);
    float pm2 = dot4(x0, sw[50 + lane]) + ((lane < 18) ? dot4(x1, sw[82 + lane]) : 0.f);

    #pragma unroll
    for (int off = 16; off; off >>= 1) {
        p1  += __shfl_xor_sync(0xffffffffu, p1, off);
        p2  += __shfl_xor_sync(0xffffffffu, p2, off);
        pm1 += __shfl_xor_sync(0xffffffffu, pm1, off);
        pm2 += __shfl_xor_sync(0xffffffffu, pm2, off);
    }
    if (lane == 0) {
        g_p[node]               = p1;
        g_p[N_NODES + node]     = p2;
        g_p[2 * N_NODES + node] = pm1;
        g_p[3 * N_NODES + node] = pm2;
    }
}

// ---------------- bf16 3x tensor-core GEMM (512 threads, 4mg x 4ng) ----------------
__device__ __forceinline__ void stage_tile(unsigned* Ah, unsigned* Al,
                                           unsigned* Bh, unsigned* Bl,
                                           const unsigned* gAh, const unsigned* gAl,
                                           int M, int row0, int jp0, int kb, int t) {
    int kp0 = kb * KP_TILE;
    // A: 640 float4 per plane
    #pragma unroll
    for (int i = 0; i < 2; i++) {
        int idx = t + i * TG_THREADS;
        if (idx < 640) {
            int r = idx / 5, c4 = idx % 5;
            bool ok = (row0 + r) < M;
            size_t go = (size_t)(row0 + r) * 100 + kp0 + c4 * 4;
            cp_async16(Ah + r * A_STRIDE + c4 * 4, gAh + go, ok);
            cp_async16(Al + r * A_STRIDE + c4 * 4, gAl + go, ok);
        }
    }
    // B: 1000 float4 per plane
    const unsigned* sH = g_bqh + (size_t)(jp0 + kp0) * FDIM;
    const unsigned* sL = g_bql + (size_t)(jp0 + kp0) * FDIM;
    #pragma unroll
    for (int i = 0; i < 2; i++) {
        int idx = t + i * TG_THREADS;
        if (idx < 1000) {
            int row = idx / 50, c4 = idx % 50;
            cp_async16(Bh + row * B_STRIDE + c4 * 4, sH + idx * 4, true);
            cp_async16(Bl + row * B_STRIDE + c4 * 4, sL + idx * 4, true);
        }
    }
}

// dest 0 -> g_X1, 1 -> g_X2, 2 -> final epilogue into fout
__global__ void __launch_bounds__(TG_THREADS, 1)
tgemm_kernel(const unsigned* __restrict__ gAh, const unsigned* __restrict__ gAl,
             int M, int jp0, int dest, float* __restrict__ fout) {
    extern __shared__ unsigned smu_[];
    unsigned* Ah[2] = { smu_, smu_ + A_BUFU };
    unsigned* Al[2] = { smu_ + 2 * A_BUFU, smu_ + 3 * A_BUFU };
    unsigned* Bh[2] = { smu_ + 4 * A_BUFU, smu_ + 4 * A_BUFU + B_BUFU };
    unsigned* Bl[2] = { smu_ + 4 * A_BUFU + 2 * B_BUFU, smu_ + 4 * A_BUFU + 3 * B_BUFU };

    int row0 = blockIdx.x * BM;
    int t = threadIdx.x;
    int warp = t >> 5, lane = t & 31;
    int mg = warp >> 2;            // 0..3 -> 32 rows each
    int ng = warp & 3;             // 0..3 -> 56 cols each (7 tiles of 8; last group guarded)
    int n0 = ng * 56;
    int m0w = mg * 32;
    int lr = lane >> 2;
    int lc = lane & 3;

    float acc[2][7][4];
    #pragma unroll
    for (int a_ = 0; a_ < 2; a_++)
        #pragma unroll
        for (int b_ = 0; b_ < 7; b_++)
            #pragma unroll
            for (int c_ = 0; c_ < 4; c_++) acc[a_][b_][c_] = 0.f;

    stage_tile(Ah[0], Al[0], Bh[0], Bl[0], gAh, gAl, M, row0, jp0, 0, t);
    cp_commit();

    for (int kb = 0; kb < NKB; kb++) {
        int cur = kb & 1;
        if (kb + 1 < NKB) {
            stage_tile(Ah[cur ^ 1], Al[cur ^ 1], Bh[cur ^ 1], Bl[cur ^ 1],
                       gAh, gAl, M, row0, jp0, kb + 1, t);
            cp_commit();
            cp_wait<1>();
        } else {
            cp_wait<0>();
        }
        __syncthreads();

        const unsigned* Ach = Ah[cur];
        const unsigned* Acl = Al[cur];
        const unsigned* Bch = Bh[cur];
        const unsigned* Bcl = Bl[cur];

        #pragma unroll
        for (int st = 0; st < 2; st++) {
            int kpb = st * 8;
            unsigned ah[2][4], al[2][4];
            #pragma unroll
            for (int mt = 0; mt < 2; mt++) {
                int mrow = m0w + mt * 16 + lr;
                ah[mt][0] = Ach[mrow * A_STRIDE + kpb + lc];
                ah[mt][1] = Ach[(mrow + 8) * A_STRIDE + kpb + lc];
                ah[mt][2] = Ach[mrow * A_STRIDE + kpb + lc + 4];
                ah[mt][3] = Ach[(mrow + 8) * A_STRIDE + kpb + lc + 4];
                al[mt][0] = Acl[mrow * A_STRIDE + kpb + lc];
                al[mt][1] = Acl[(mrow + 8) * A_STRIDE + kpb + lc];
                al[mt][2] = Acl[mrow * A_STRIDE + kpb + lc + 4];
                al[mt][3] = Acl[(mrow + 8) * A_STRIDE + kpb + lc + 4];
            }
            #pragma unroll
            for (int nt = 0; nt < 7; nt++) {
                int nc = n0 + nt * 8 + lr;
                unsigned bh0 = Bch[(kpb + lc) * B_STRIDE + nc];
                unsigned bh1 = Bch[(kpb + lc + 4) * B_STRIDE + nc];
                unsigned bl0 = Bcl[(kpb + lc) * B_STRIDE + nc];
                unsigned bl1 = Bcl[(kpb + lc + 4) * B_STRIDE + nc];
                #pragma unroll
                for (int mt = 0; mt < 2; mt++) {
                    mma_bf16_k16(acc[mt][nt], ah[mt], bh0, bh1);
                    mma_bf16_k16(acc[mt][nt], ah[mt], bl0, bl1);
                    mma_bf16_k16(acc[mt][nt], al[mt], bh0, bh1);
                }
            }
        }
        {
            unsigned ah8[2][2], al8[2][2];
            #pragma unroll
            for (int mt = 0; mt < 2; mt++) {
                int mrow = m0w + mt * 16 + lr;
                ah8[mt][0] = Ach[mrow * A_STRIDE + 16 + lc];
                ah8[mt][1] = Ach[(mrow + 8) * A_STRIDE + 16 + lc];
                al8[mt][0] = Acl[mrow * A_STRIDE + 16 + lc];
                al8[mt][1] = Acl[(mrow + 8) * A_STRIDE + 16 + lc];
            }
            #pragma unroll
            for (int nt = 0; nt < 7; nt++) {
                int nc = n0 + nt * 8 + lr;
                unsigned bh0 = Bch[(16 + lc) * B_STRIDE + nc];
                unsigned bl0 = Bcl[(16 + lc) * B_STRIDE + nc];
                #pragma unroll
                for (int mt = 0; mt < 2; mt++) {
                    mma_bf16_k8(acc[mt][nt], ah8[mt][0], ah8[mt][1], bh0);
                    mma_bf16_k8(acc[mt][nt], ah8[mt][0], ah8[mt][1], bl0);
                    mma_bf16_k8(acc[mt][nt], al8[mt][0], al8[mt][1], bh0);
                }
            }
        }
        __syncthreads();
    }

    if (dest != 2) {
        float* Out = (dest == 0) ? g_X1 : g_X2;
        #pragma unroll
        for (int mt = 0; mt < 2; mt++) {
            int r0 = row0 + m0w + mt * 16 + lr;
            #pragma unroll
            for (int nt = 0; nt < 7; nt++) {
                int col = n0 + nt * 8 + 2 * lc;
                if (col >= FDIM) continue;
                if (r0 < M)
                    *(float2*)(Out + (size_t)r0 * FDIM + col) =
                        make_float2(acc[mt][nt][0], acc[mt][nt][1]);
                if (r0 + 8 < M)
                    *(float2*)(Out + (size_t)(r0 + 8) * FDIM + col) =
                        make_float2(acc[mt][nt][2], acc[mt][nt][3]);
            }
        }
    } else {
        #pragma unroll
        for (int mt = 0; mt < 2; mt++) {
            #pragma unroll
            for (int h = 0; h < 2; h++) {
                int r = row0 + m0w + mt * 16 + lr + 8 * h;
                if (r >= M) continue;
                float rs = g_rs[r];
                if (rs == 0.f) {
                    #pragma unroll
                    for (int nt = 0; nt < 7; nt++) {
                        int col = n0 + nt * 8 + 2 * lc;
                        if (col >= FDIM) continue;
                        *(float2*)(fout + (size_t)r * FDIM + col) = make_float2(0.f, 0.f);
                    }
                } else {
                    float inv = 1.f / rs;
                    #pragma unroll
                    for (int nt = 0; nt < 7; nt++) {
                        int col = n0 + nt * 8 + 2 * lc;
                        if (col >= FDIM) continue;
                        size_t idx = (size_t)r * FDIM + col;
                        float2 x1 = *(const float2*)(g_X1 + idx);
                        float2 av = *(const float2*)(g_ACC + idx);
                        float g0 = acc[mt][nt][2 * h + 0];
                        float g1 = acc[mt][nt][2 * h + 1];
                        float v0 = x1.x + (av.x + g0) * inv;
                        float v1 = x1.y + (av.y + g1) * inv;
                        v0 = (v0 > 0.f) ? v0 : (expf(v0) - 1.f);
                        v1 = (v1 > 0.f) ? v1 : (expf(v1) - 1.f);
                        *(float2*)(fout + idx) = make_float2(v0, v1);
                    }
                }
            }
        }
    }
}

// ---------------- phase 1: streaming edge scores ----------------
__global__ __launch_bounds__(256) void score_kernel(const int* __restrict__ edge,
                                                    const float* __restrict__ emb1,
                                                    const int* __restrict__ edge2,
                                                    const float* __restrict__ emb2,
                                                    const float* __restrict__ mlp_b) {
    __shared__ float4 sv[50];
    __shared__ float4 sw[50];
    int t = threadIdx.x;
    if (t < 50)       sv[t]      = *(const float4*)&g_v[400 + t * 4];
    else if (t < 100) sw[t - 50] = *(const float4*)&g_w[400 + (t - 50) * 4];
    __syncthreads();

    int warp = t >> 5, lane = t & 31;
    int eid = blockIdx.x * 8 + warp;
    if (eid >= E_TOT) return;

    int src, dst;
    const float4* emb;
    if (eid < E1C) {
        src = edge[eid];
        dst = edge[E1C + eid];
        emb = (const float4*)emb1 + (size_t)eid * 50;
    } else {
        int e2 = eid - E1C;
        src = edge2[e2];
        dst = edge2[E2C + e2];
        emb = (const float4*)emb2 + (size_t)e2 * 50;
    }

    float4 m0 = emb[lane];
    float4 m1 = (lane < 18) ? emb[32 + lane] : make_float4(0, 0, 0, 0);

    float q3 = dot4(m0, sv[lane]) + ((lane < 18) ? dot4(m1, sv[32 + lane]) : 0.f);
    float qm = dot4(m0, sw[lane]) + ((lane < 18) ? dot4(m1, sw[32 + lane]) : 0.f);
    #pragma unroll
    for (int off = 16; off; off >>= 1) {
        q3 += __shfl_xor_sync(0xffffffffu, q3, off);
        qm += __shfl_xor_sync(0xffffffffu, qm, off);
    }

    if (lane == 0) {
        float sa = g_p[src] + g_p[N_NODES + dst] + q3;
        float sm = g_p[2 * N_NODES + src] + g_p[3 * N_NODES + dst] + qm + mlp_b[0];
        float lrv = (sa > 0.f) ? sa : ALPHA * sa;
        float pw = -lrv * tanh_fast(sm) * (1.0f / (float)E_TOT);
        g_ee[eid] = __expf(pw);
    }
}

// ---------------- phase 2: role-split gather (G written packed bf16) ----------------
__global__ __launch_bounds__(256) void gather_kernel(const float* __restrict__ emb1,
                                                     const float* __restrict__ emb2) {
    int t = threadIdx.x;
    int warp = t >> 5, lane = t & 31;
    int node = blockIdx.x * 4 + (warp >> 1);
    int role = warp & 1;
    if (node >= N_NODES) return;

    int beg = g_off[node];
    int end = g_off[node + 1];

    float4 a0 = make_float4(0, 0, 0, 0), a1 = a0;
    float rs = 0.f;

    for (int base = beg; base < end; base += 32) {
        int cnt = min(32, end - base);
        int4 rr = (lane < cnt) ? g_rec3[base + lane] : make_int4(0, 0, 0, 0);

        int j = 0;
        for (; j + 4 <= cnt; j += 4) {
            const float4* p[4];
            float e[4];
            #pragma unroll
            for (int k = 0; k < 4; k++) {
                int dstk = __shfl_sync(0xffffffffu, rr.x, j + k);
                int eidk = __shfl_sync(0xffffffffu, rr.y, j + k);
                e[k] = __int_as_float(__shfl_sync(0xffffffffu, rr.z, j + k));
                if (role == 0) {
                    p[k] = (eidk < E1C) ? (const float4*)emb1 + (size_t)eidk * 50
                                        : (const float4*)emb2 + (size_t)(eidk - E1C) * 50;
                } else {
                    p[k] = (const float4*)g_X2 + (size_t)dstk * 50;
                }
            }
            float4 v[4], u[4];
            #pragma unroll
            for (int k = 0; k < 4; k++) v[k] = p[k][lane];
            if (lane < 18) {
                #pragma unroll
                for (int k = 0; k < 4; k++) u[k] = p[k][32 + lane];
            }
            #pragma unroll
            for (int k = 0; k < 4; k++) {
                rs += e[k];
                a0.x += e[k] * v[k].x; a0.y += e[k] * v[k].y;
                a0.z += e[k] * v[k].z; a0.w += e[k] * v[k].w;
            }
            if (lane < 18) {
                #pragma unroll
                for (int k = 0; k < 4; k++) {
                    a1.x += e[k] * u[k].x; a1.y += e[k] * u[k].y;
                    a1.z += e[k] * u[k].z; a1.w += e[k] * u[k].w;
                }
            }
        }
        for (; j < cnt; j++) {
            int dst0 = __shfl_sync(0xffffffffu, rr.x, j);
            int eid0 = __shfl_sync(0xffffffffu, rr.y, j);
            float e0 = __int_as_float(__shfl_sync(0xffffffffu, rr.z, j));
            const float4* p0;
            if (role == 0) {
                p0 = (eid0 < E1C) ? (const float4*)emb1 + (size_t)eid0 * 50
                                  : (const float4*)emb2 + (size_t)(eid0 - E1C) * 50;
            } else {
                p0 = (const float4*)g_X2 + (size_t)dst0 * 50;
            }
            float4 v0 = p0[lane];
            rs += e0;
            a0.x += e0 * v0.x; a0.y += e0 * v0.y; a0.z += e0 * v0.z; a0.w += e0 * v0.w;
            if (lane < 18) {
                float4 u0 = p0[32 + lane];
                a1.x += e0 * u0.x; a1.y += e0 * u0.y; a1.z += e0 * u0.z; a1.w += e0 * u0.w;
            }
        }
    }

    if (role == 0) {
        unsigned h0, l0, h1, l1;
        split_pack2(a0.x, a0.y, h0, l0);
        split_pack2(a0.z, a0.w, h1, l1);
        size_t o = (size_t)node * 100 + 2 * lane;
        *(uint2*)&g_gqh[o] = make_uint2(h0, h1);
        *(uint2*)&g_gql[o] = make_uint2(l0, l1);
        if (lane < 18) {
            split_pack2(a1.x, a1.y, h0, l0);
            split_pack2(a1.z, a1.w, h1, l1);
            size_t o2 = (size_t)node * 100 + 64 + 2 * lane;
            *(uint2*)&g_gqh[o2] = make_uint2(h0, h1);
            *(uint2*)&g_gql[o2] = make_uint2(l0, l1);
        }
        if (lane == 0) g_rs[node] = rs;
    } else {
        float4* Out = (float4*)g_ACC + (size_t)node * 50;
        Out[lane] = a0;
        if (lane < 18) Out[32 + lane] = a1;
    }
}

// ---- streams/events created once at load time ----
struct GraphResources {
    cudaStream_t s1, s2;
    cudaEvent_t evStart, evT, evX2, evX1, evCSR;
    GraphResources() {
        cudaStreamCreateWithFlags(&s1, cudaStreamNonBlocking);
        cudaStreamCreateWithFlags(&s2, cudaStreamNonBlocking);
        cudaEventCreateWithFlags(&evStart, cudaEventDisableTiming);
        cudaEventCreateWithFlags(&evT, cudaEventDisableTiming);
        cudaEventCreateWithFlags(&evX2, cudaEventDisableTiming);
        cudaEventCreateWithFlags(&evX1, cudaEventDisableTiming);
        cudaEventCreateWithFlags(&evCSR, cudaEventDisableTiming);
    }
};
static GraphResources g_gr;

extern "C" void kernel_launch(void* const* d_in, const int* in_sizes, int n_in,
                              void* d_out, int out_size) {
    const float* x    = (const float*)d_in[0];
    const int*   edge = (const int*)  d_in[1];
    const float* ee1  = (const float*)d_in[2];
    const int*   edg2 = (const int*)  d_in[3];
    const float* ee2  = (const float*)d_in[4];
    const float* a    = (const float*)d_in[5];
    const float* a2   = (const float*)d_in[6];
    const float* mw   = (const float*)d_in[7];
    const float* mb   = (const float*)d_in[8];
    float* out = (float*)d_out;

    cudaFuncSetAttribute(tgemm_kernel, cudaFuncAttributeMaxDynamicSharedMemorySize, SMEM_BYTES);

    int ggrid = (N_NODES + BM - 1) / BM;
    cudaStream_t s0 = 0;

    unsigned *xqh_p, *xql_p, *gqh_p, *gql_p;
    cudaGetSymbolAddress((void**)&xqh_p, g_xqh);
    cudaGetSymbolAddress((void**)&xql_p, g_xql);
    cudaGetSymbolAddress((void**)&gqh_p, g_gqh);
    cudaGetSymbolAddress((void**)&gql_p, g_gql);

    cudaEventRecord(g_gr.evStart, s0);

    // main stream: prep (launches 1-3), then GEMMs on s2 (4th launch = X2 tgemm, profiled)
    transpose_kernel<<<(300 * FDIM + 255) / 256, 256, 0, s0>>>(a);
    vw_kernel<<<1, 640, 0, s0>>>(a, a2, mw);
    pack_x_kernel<<<(N_NODES * 50 + 255) / 256, 256, 0, s0>>>(x);
    cudaEventRecord(g_gr.evT, s0);

    cudaStreamWaitEvent(g_gr.s2, g_gr.evT, 0);
    tgemm_kernel<<<ggrid, TG_THREADS, SMEM_BYTES, g_gr.s2>>>(xqh_p, xql_p, N_NODES, 100, 1, nullptr);  // X2
    cudaEventRecord(g_gr.evX2, g_gr.s2);
    tgemm_kernel<<<ggrid, TG_THREADS, SMEM_BYTES, g_gr.s2>>>(xqh_p, xql_p, N_NODES, 0, 0, nullptr);    // X1
    cudaEventRecord(g_gr.evX1, g_gr.s2);

    // main stream: pvec + streaming scores (overlaps GEMMs)
    pvec_kernel<<<N_NODES / 8, 256, 0, s0>>>(x);
    score_kernel<<<E_TOT / 8, 256, 0, s0>>>(edge, ee1, edg2, ee2, mb);

    // s1: CSR build
    cudaStreamWaitEvent(g_gr.s1, g_gr.evStart, 0);
    zero_deg_kernel<<<(N_NODES + 255) / 256, 256, 0, g_gr.s1>>>();
    deg_kernel<<<(E_TOT + 255) / 256, 256, 0, g_gr.s1>>>(edge, edg2);
    scan_kernel<<<1, 1024, 0, g_gr.s1>>>();
    fill_kernel<<<(E_TOT + 255) / 256, 256, 0, g_gr.s1>>>(edge, edg2);
    cudaEventRecord(g_gr.evCSR, g_gr.s1);

    // pack recs (needs score + CSR), gather (needs pack + X2)
    cudaStreamWaitEvent(s0, g_gr.evCSR, 0);
    pack_kernel<<<(E_TOT + 255) / 256, 256, 0, s0>>>();
    cudaStreamWaitEvent(s0, g_gr.evX2, 0);
    gather_kernel<<<(N_NODES + 3) / 4, 256, 0, s0>>>(ee1, ee2);

    cudaStreamWaitEvent(s0, g_gr.evX1, 0);
    tgemm_kernel<<<ggrid, TG_THREADS, SMEM_BYTES, s0>>>(gqh_p, gql_p, N_NODES, 200, 2, out);  // final
}